// round 2
// baseline (speedup 1.0000x reference)
#include <cuda_runtime.h>
#include <cuda_bf16.h>
#include <cstdint>
#include <cstdio>

#define BATCH 4
#define CCH   256
#define HWN   4096
#define MID   64

// ---------------- scratch (static device globals; no runtime allocation) ----------------
__device__ __nv_bfloat16 g_Ut[BATCH * HWN * CCH];          // U^T  [b][j][c]     8 MB
__device__ __nv_bfloat16 g_Qt[BATCH * HWN * CCH];          // Q^T  [b][j][o]     8 MB
__device__ __nv_bfloat16 g_Kt[BATCH * HWN * CCH];          // K^T  [b][i][o]     8 MB
__device__ __nv_bfloat16 g_V [BATCH * CCH * HWN];          // V    [b][c][i]     8 MB
__device__ __nv_bfloat16 g_T [BATCH * HWN * MID];          // key mid [b][i][m]  2 MB
__device__ __nv_bfloat16 g_S [(size_t)BATCH * HWN * HWN];  // S/P [b][j][i]    128 MB
__device__ __nv_bfloat16 g_Wq[CCH * CCH];
__device__ __nv_bfloat16 g_Wv[CCH * CCH];
__device__ __nv_bfloat16 g_W2[CCH * MID];
__device__ float g_pm[BATCH * 16 * HWN];
__device__ float g_pz[BATCH * 16 * HWN];
__device__ float g_M [BATCH * HWN];
__device__ float g_Zi[BATCH * HWN];

// ---------------- small helpers ----------------
__device__ __forceinline__ uint32_t smem_u32(const void* p) {
    return (uint32_t)__cvta_generic_to_shared(p);
}

__device__ __forceinline__ void ldsm4(uint32_t& r0, uint32_t& r1, uint32_t& r2, uint32_t& r3, uint32_t a) {
    asm volatile("ldmatrix.sync.aligned.m8n8.x4.shared.b16 {%0,%1,%2,%3},[%4];\n"
                 : "=r"(r0), "=r"(r1), "=r"(r2), "=r"(r3) : "r"(a));
}

__device__ __forceinline__ void mma_bf16(float acc[4],
                                         uint32_t a0, uint32_t a1, uint32_t a2, uint32_t a3,
                                         uint32_t b0, uint32_t b1) {
    asm volatile(
        "mma.sync.aligned.m16n8k16.row.col.f32.bf16.bf16.f32 "
        "{%0,%1,%2,%3}, {%4,%5,%6,%7}, {%8,%9}, {%0,%1,%2,%3};\n"
        : "+f"(acc[0]), "+f"(acc[1]), "+f"(acc[2]), "+f"(acc[3])
        : "r"(a0), "r"(a1), "r"(a2), "r"(a3), "r"(b0), "r"(b1));
}

// ---------------- prep kernels ----------------
__global__ void k_prep_weights(const float* __restrict__ wq,
                               const float* __restrict__ wv,
                               const float* __restrict__ w2) {
    int i = blockIdx.x * blockDim.x + threadIdx.x;
    if (i < CCH * CCH) g_Wq[i] = __float2bfloat16(wq[i]);
    if (i < CCH * CCH) g_Wv[i] = __float2bfloat16(wv[i]);
    if (i < CCH * MID) g_W2[i] = __float2bfloat16(w2[i]);
}

// U [b][c][j] f32  ->  Ut [b][j][c] bf16
__global__ void k_transpose_U(const float* __restrict__ U) {
    __shared__ float tile[32][33];
    int b = blockIdx.z;
    int j0 = blockIdx.x * 32, c0 = blockIdx.y * 32;
    int tx = threadIdx.x, ty = threadIdx.y;
    const float* Ub = U + (size_t)b * CCH * HWN;
#pragma unroll
    for (int r = 0; r < 4; r++)
        tile[ty + r * 8][tx] = Ub[(size_t)(c0 + ty + r * 8) * HWN + j0 + tx];
    __syncthreads();
    __nv_bfloat16* Utb = g_Ut + (size_t)b * HWN * CCH;
#pragma unroll
    for (int r = 0; r < 4; r++)
        Utb[(size_t)(j0 + ty + r * 8) * CCH + c0 + tx] = __float2bfloat16(tile[tx][ty + r * 8]);
}

// T[b][i][m] = relu( a_m * bm(b,i) + c_m ),  bm = nearest-downsampled boundary map
__global__ void k_compute_T(const float* __restrict__ bmap, const float* __restrict__ kw1,
                            const float* __restrict__ sc, const float* __restrict__ bi,
                            const float* __restrict__ mu, const float* __restrict__ var) {
    __shared__ float sA[MID], sC[MID];
    int tid = threadIdx.x;
    if (tid < MID) {
        float inv = sc[tid] * rsqrtf(var[tid] + 1e-5f);
        sA[tid] = kw1[tid] * inv;
        sC[tid] = bi[tid] - mu[tid] * inv;
    }
    __syncthreads();
    int p  = blockIdx.x * 4 + (tid >> 6);   // flattened (b,i)
    int m  = tid & 63;
    int b  = p >> 12, i = p & 4095;
    int ih = i >> 6, iw = i & 63;
    float x = bmap[b * 16384 + (ih * 2) * 128 + iw * 2];
    float t = fmaxf(x * sA[m] + sC[m], 0.f);
    g_T[(size_t)p * MID + m] = __float2bfloat16(t);
}

// ---------------- generic TN bf16 GEMM: C[m][n] = sum_k A[m][k] B[n][k] ----------------
// BM=BN=128, BK=64, 256 threads (2x4 warps, warp tile 64x32), smem XOR-swizzled.
// OUT_MODE 0: store bf16 to Cb ([b][m][n], ld=N)
// OUT_MODE 1: Cf[b][m][n] = gamma*acc + Ures[b][m][n] (f32)
template <int OUT_MODE>
__global__ __launch_bounds__(256)
void k_gemm_tn(const __nv_bfloat16* __restrict__ A, long strideA,
               const __nv_bfloat16* __restrict__ Bm, long strideB,
               int lda, int ldb, int M, int N, int K,
               __nv_bfloat16* __restrict__ Cb, long strideC,
               float* __restrict__ Cf, const float* __restrict__ Ures,
               const float* __restrict__ gamma) {
    __shared__ __align__(16) __nv_bfloat16 As[128 * 64];
    __shared__ __align__(16) __nv_bfloat16 Bs[128 * 64];

    int b  = blockIdx.z;
    int n0 = blockIdx.x * 128, m0 = blockIdx.y * 128;
    const __nv_bfloat16* Ab = A + (size_t)b * strideA;
    const __nv_bfloat16* Bb = Bm + (size_t)b * strideB;

    int tid = threadIdx.x;
    int warp = tid >> 5, lane = tid & 31;
    int wm = warp >> 2, wn = warp & 3;  // 2 x 4 warp grid

    float acc[4][4][4];
#pragma unroll
    for (int a = 0; a < 4; a++)
#pragma unroll
        for (int c = 0; c < 4; c++)
#pragma unroll
            for (int d = 0; d < 4; d++) acc[a][c][d] = 0.f;

    uint32_t sA = smem_u32(As), sB = smem_u32(Bs);

    for (int k0 = 0; k0 < K; k0 += 64) {
        // load tiles (16B chunks, XOR swizzle: chunk' = chunk ^ (row & 7))
#pragma unroll
        for (int it = 0; it < 4; it++) {
            int q = tid + it * 256;
            int r = q >> 3, c = q & 7;
            uint4 v = *reinterpret_cast<const uint4*>(Ab + (size_t)(m0 + r) * lda + k0 + c * 8);
            *reinterpret_cast<uint4*>(As + r * 64 + ((c ^ (r & 7)) << 3)) = v;
        }
#pragma unroll
        for (int it = 0; it < 4; it++) {
            int q = tid + it * 256;
            int r = q >> 3, c = q & 7;
            uint4 v = *reinterpret_cast<const uint4*>(Bb + (size_t)(n0 + r) * ldb + k0 + c * 8);
            *reinterpret_cast<uint4*>(Bs + r * 64 + ((c ^ (r & 7)) << 3)) = v;
        }
        __syncthreads();

#pragma unroll
        for (int kk = 0; kk < 4; kk++) {
            uint32_t afr[4][4];
#pragma unroll
            for (int mi = 0; mi < 4; mi++) {
                int row = wm * 64 + mi * 16 + (lane & 15);
                int ch  = kk * 2 + (lane >> 4);
                uint32_t ad = sA + ((row << 6) + ((ch ^ (row & 7)) << 3)) * 2;
                ldsm4(afr[mi][0], afr[mi][1], afr[mi][2], afr[mi][3], ad);
            }
            uint32_t bfr[4][2];
#pragma unroll
            for (int nb = 0; nb < 2; nb++) {
                int row = wn * 32 + nb * 16 + (lane & 7) + ((lane >> 4) << 3);
                int ch  = kk * 2 + ((lane >> 3) & 1);
                uint32_t ad = sB + ((row << 6) + ((ch ^ (row & 7)) << 3)) * 2;
                uint32_t r0, r1, r2, r3;
                ldsm4(r0, r1, r2, r3, ad);
                bfr[nb * 2][0] = r0; bfr[nb * 2][1] = r1;
                bfr[nb * 2 + 1][0] = r2; bfr[nb * 2 + 1][1] = r3;
            }
#pragma unroll
            for (int mi = 0; mi < 4; mi++)
#pragma unroll
                for (int ni = 0; ni < 4; ni++)
                    mma_bf16(acc[mi][ni], afr[mi][0], afr[mi][1], afr[mi][2], afr[mi][3],
                             bfr[ni][0], bfr[ni][1]);
        }
        __syncthreads();
    }

    // epilogue
    int mb = m0 + wm * 64;
    int nb = n0 + wn * 32;
    float g = 0.f;
    if (OUT_MODE == 1) g = gamma[0];
#pragma unroll
    for (int mi = 0; mi < 4; mi++) {
#pragma unroll
        for (int ni = 0; ni < 4; ni++) {
            int m = mb + mi * 16 + (lane >> 2);
            int n = nb + ni * 8 + (lane & 3) * 2;
            float* a = acc[mi][ni];
            if (OUT_MODE == 0) {
                __nv_bfloat16* base = Cb + (size_t)b * strideC;
                *reinterpret_cast<__nv_bfloat162*>(base + (size_t)m * N + n) =
                    __float22bfloat162_rn(make_float2(a[0], a[1]));
                *reinterpret_cast<__nv_bfloat162*>(base + (size_t)(m + 8) * N + n) =
                    __float22bfloat162_rn(make_float2(a[2], a[3]));
            } else {
                size_t o1 = (size_t)b * M * N + (size_t)m * N + n;
                size_t o2 = o1 + 8 * (size_t)N;
                float2 u1 = *reinterpret_cast<const float2*>(Ures + o1);
                float2 u2 = *reinterpret_cast<const float2*>(Ures + o2);
                float2 r1 = make_float2(g * a[0] + u1.x, g * a[1] + u1.y);
                float2 r2 = make_float2(g * a[2] + u2.x, g * a[3] + u2.y);
                *reinterpret_cast<float2*>(Cf + o1) = r1;
                *reinterpret_cast<float2*>(Cf + o2) = r2;
            }
        }
    }
}

// ---------------- softmax over j (per column i of S[b][j][i]) ----------------
__global__ void k_stats_partial() {
    int b = blockIdx.z, js = blockIdx.y, ib = blockIdx.x;
    int i = ib * 256 + threadIdx.x;
    const __nv_bfloat16* Sb = g_S + (size_t)b * HWN * HWN + i;
    float m = -1e30f, z = 0.f;
    int j0 = js * 256;
    for (int j = 0; j < 256; j++) {
        float s  = __bfloat162float(Sb[(size_t)(j0 + j) * HWN]);
        float mo = m;
        m = fmaxf(m, s);
        z = z * __expf(mo - m) + __expf(s - m);
    }
    g_pm[(b * 16 + js) * HWN + i] = m;
    g_pz[(b * 16 + js) * HWN + i] = z;
}

__global__ void k_stats_combine() {
    int idx = blockIdx.x * blockDim.x + threadIdx.x;  // b*4096 + i
    int b = idx >> 12, i = idx & 4095;
    float m = -1e30f;
#pragma unroll
    for (int p = 0; p < 16; p++) m = fmaxf(m, g_pm[(b * 16 + p) * HWN + i]);
    float z = 0.f;
#pragma unroll
    for (int p = 0; p < 16; p++)
        z += g_pz[(b * 16 + p) * HWN + i] * __expf(g_pm[(b * 16 + p) * HWN + i] - m);
    g_M[idx]  = m;
    g_Zi[idx] = 1.f / z;
}

// S[b][j][i] <- exp(S - m_i) * zinv_i  (in place, 8 bf16 per thread)
__global__ void k_normalize() {
    size_t t   = (size_t)blockIdx.x * blockDim.x + threadIdx.x;
    size_t off = t * 8;
    int b  = (int)(off >> 24);          // 4096*4096 = 2^24
    int i0 = (int)(off & 4095);
    uint4 v = *reinterpret_cast<const uint4*>(g_S + off);
    const float* Mb = g_M + b * HWN + i0;
    const float* Zb = g_Zi + b * HWN + i0;
    __nv_bfloat162* h = reinterpret_cast<__nv_bfloat162*>(&v);
    uint4 w;
    __nv_bfloat162* ho = reinterpret_cast<__nv_bfloat162*>(&w);
#pragma unroll
    for (int q = 0; q < 4; q++) {
        float2 f = __bfloat1622float2(h[q]);
        float p0 = __expf(f.x - Mb[q * 2 + 0]) * Zb[q * 2 + 0];
        float p1 = __expf(f.y - Mb[q * 2 + 1]) * Zb[q * 2 + 1];
        ho[q] = __float22bfloat162_rn(make_float2(p0, p1));
    }
    *reinterpret_cast<uint4*>(g_S + off) = w;
}

// ---------------- launch ----------------
extern "C" void kernel_launch(void* const* d_in, const int* in_sizes, int n_in,
                              void* d_out, int out_size) {
    const float* bmap = (const float*)d_in[0];
    const float* U    = (const float*)d_in[1];
    const float* kw1  = (const float*)d_in[2];
    const float* bsc  = (const float*)d_in[3];
    const float* bbi  = (const float*)d_in[4];
    const float* bmu  = (const float*)d_in[5];
    const float* bva  = (const float*)d_in[6];
    const float* w2   = (const float*)d_in[7];
    const float* wq   = (const float*)d_in[8];
    const float* wv   = (const float*)d_in[9];
    const float* gam  = (const float*)d_in[10];
    float* out = (float*)d_out;

    void *pUt, *pQt, *pKt, *pV, *pT, *pS, *pWq, *pWv, *pW2;
    cudaGetSymbolAddress(&pUt, g_Ut);
    cudaGetSymbolAddress(&pQt, g_Qt);
    cudaGetSymbolAddress(&pKt, g_Kt);
    cudaGetSymbolAddress(&pV,  g_V);
    cudaGetSymbolAddress(&pT,  g_T);
    cudaGetSymbolAddress(&pS,  g_S);
    cudaGetSymbolAddress(&pWq, g_Wq);
    cudaGetSymbolAddress(&pWv, g_Wv);
    cudaGetSymbolAddress(&pW2, g_W2);
    __nv_bfloat16* Ut = (__nv_bfloat16*)pUt;
    __nv_bfloat16* Qt = (__nv_bfloat16*)pQt;
    __nv_bfloat16* Kt = (__nv_bfloat16*)pKt;
    __nv_bfloat16* V  = (__nv_bfloat16*)pV;
    __nv_bfloat16* T  = (__nv_bfloat16*)pT;
    __nv_bfloat16* S  = (__nv_bfloat16*)pS;
    __nv_bfloat16* Wq = (__nv_bfloat16*)pWq;
    __nv_bfloat16* Wv = (__nv_bfloat16*)pWv;
    __nv_bfloat16* W2 = (__nv_bfloat16*)pW2;

    k_prep_weights<<<256, 256>>>(wq, wv, w2);
    k_transpose_U<<<dim3(128, 8, BATCH), dim3(32, 8)>>>(U);
    k_compute_T<<<4096, 256>>>(bmap, kw1, bsc, bbi, bmu, bva);

    // Qt[b][j][o] = sum_c Ut[j][c] * Wq[o][c]          M=4096 N=256 K=256
    k_gemm_tn<0><<<dim3(2, 32, BATCH), 256>>>(Ut, (long)HWN * CCH, Wq, 0,
                                              CCH, CCH, HWN, CCH, CCH,
                                              Qt, (long)HWN * CCH, nullptr, nullptr, nullptr);
    // Kt[b][i][o] = sum_m T[i][m] * W2[o][m]           M=4096 N=256 K=64
    k_gemm_tn<0><<<dim3(2, 32, BATCH), 256>>>(T, (long)HWN * MID, W2, 0,
                                              MID, MID, HWN, CCH, MID,
                                              Kt, (long)HWN * CCH, nullptr, nullptr, nullptr);
    // V[b][o][j] = sum_c Wv[o][c] * Ut[j][c]           M=256 N=4096 K=256
    k_gemm_tn<0><<<dim3(32, 2, BATCH), 256>>>(Wv, 0, Ut, (long)HWN * CCH,
                                              CCH, CCH, CCH, HWN, CCH,
                                              V, (long)CCH * HWN, nullptr, nullptr, nullptr);
    // S[b][j][i] = sum_o Qt[j][o] * Kt[i][o]           M=4096 N=4096 K=256
    k_gemm_tn<0><<<dim3(32, 32, BATCH), 256>>>(Qt, (long)HWN * CCH, Kt, (long)HWN * CCH,
                                               CCH, CCH, HWN, HWN, CCH,
                                               S, (long)HWN * HWN, nullptr, nullptr, nullptr);

    k_stats_partial<<<dim3(16, 16, BATCH), 256>>>();
    k_stats_combine<<<64, 256>>>();
    k_normalize<<<32768, 256>>>();

    // out[b][c][j] = gamma * sum_i V[c][i] * P[j][i] + U[b][c][j]   M=256 N=4096 K=4096
    k_gemm_tn<1><<<dim3(32, 2, BATCH), 256>>>(V, (long)CCH * HWN, S, (long)HWN * HWN,
                                              HWN, HWN, CCH, HWN, HWN,
                                              nullptr, 0, out, U, gam);
}

// round 3
// speedup vs baseline: 1.0119x; 1.0119x over previous
#include <cuda_runtime.h>
#include <cuda_bf16.h>
#include <cstdint>
#include <cstdio>

#define BATCH 4
#define CCH   256
#define HWN   4096
#define MID   64

// ---------------- scratch (static device globals; no runtime allocation) ----------------
__device__ __nv_bfloat16 g_Ut[BATCH * HWN * CCH];          // U^T  [b][j][c]     8 MB
__device__ __nv_bfloat16 g_Qt[BATCH * HWN * CCH];          // Q^T  [b][j][o]     8 MB
__device__ __nv_bfloat16 g_Kt[BATCH * HWN * CCH];          // K^T  [b][i][o]     8 MB
__device__ __nv_bfloat16 g_V [BATCH * CCH * HWN];          // V    [b][c][i]     8 MB
__device__ __nv_bfloat16 g_T [BATCH * HWN * MID];          // key mid [b][i][m]  2 MB
__device__ __nv_bfloat16 g_S [(size_t)BATCH * HWN * HWN];  // S/P [b][j][i]    128 MB
__device__ __nv_bfloat16 g_Wq[CCH * CCH];
__device__ __nv_bfloat16 g_Wv[CCH * CCH];
__device__ __nv_bfloat16 g_W2[CCH * MID];
__device__ float g_pm[BATCH * 16 * HWN];
__device__ float g_pz[BATCH * 16 * HWN];
__device__ float g_M [BATCH * HWN];
__device__ float g_Zi[BATCH * HWN];

// ---------------- small helpers ----------------
__device__ __forceinline__ uint32_t smem_u32(const void* p) {
    return (uint32_t)__cvta_generic_to_shared(p);
}

__device__ __forceinline__ void ldsm4(uint32_t& r0, uint32_t& r1, uint32_t& r2, uint32_t& r3, uint32_t a) {
    asm volatile("ldmatrix.sync.aligned.m8n8.x4.shared.b16 {%0,%1,%2,%3},[%4];\n"
                 : "=r"(r0), "=r"(r1), "=r"(r2), "=r"(r3) : "r"(a));
}

__device__ __forceinline__ void mma_bf16(float acc[4],
                                         uint32_t a0, uint32_t a1, uint32_t a2, uint32_t a3,
                                         uint32_t b0, uint32_t b1) {
    asm volatile(
        "mma.sync.aligned.m16n8k16.row.col.f32.bf16.bf16.f32 "
        "{%0,%1,%2,%3}, {%4,%5,%6,%7}, {%8,%9}, {%0,%1,%2,%3};\n"
        : "+f"(acc[0]), "+f"(acc[1]), "+f"(acc[2]), "+f"(acc[3])
        : "r"(a0), "r"(a1), "r"(a2), "r"(a3), "r"(b0), "r"(b1));
}

// ---------------- prep kernels ----------------
__global__ void k_prep_weights(const float* __restrict__ wq,
                               const float* __restrict__ wv,
                               const float* __restrict__ w2) {
    int i = blockIdx.x * blockDim.x + threadIdx.x;
    if (i < CCH * CCH) g_Wq[i] = __float2bfloat16(wq[i]);
    if (i < CCH * CCH) g_Wv[i] = __float2bfloat16(wv[i]);
    if (i < CCH * MID) g_W2[i] = __float2bfloat16(w2[i]);
}

// U [b][c][j] f32  ->  Ut [b][j][c] bf16
__global__ void k_transpose_U(const float* __restrict__ U) {
    __shared__ float tile[32][33];
    int b = blockIdx.z;
    int j0 = blockIdx.x * 32, c0 = blockIdx.y * 32;
    int tx = threadIdx.x, ty = threadIdx.y;
    const float* Ub = U + (size_t)b * CCH * HWN;
#pragma unroll
    for (int r = 0; r < 4; r++)
        tile[ty + r * 8][tx] = Ub[(size_t)(c0 + ty + r * 8) * HWN + j0 + tx];
    __syncthreads();
    __nv_bfloat16* Utb = g_Ut + (size_t)b * HWN * CCH;
#pragma unroll
    for (int r = 0; r < 4; r++)
        Utb[(size_t)(j0 + ty + r * 8) * CCH + c0 + tx] = __float2bfloat16(tile[tx][ty + r * 8]);
}

// T[b][i][m] = relu( a_m * bm(b,i) + c_m ),  bm = nearest-downsampled boundary map
__global__ void k_compute_T(const float* __restrict__ bmap, const float* __restrict__ kw1,
                            const float* __restrict__ sc, const float* __restrict__ bi,
                            const float* __restrict__ mu, const float* __restrict__ var) {
    __shared__ float sA[MID], sC[MID];
    int tid = threadIdx.x;
    if (tid < MID) {
        float inv = sc[tid] * rsqrtf(var[tid] + 1e-5f);
        sA[tid] = kw1[tid] * inv;
        sC[tid] = bi[tid] - mu[tid] * inv;
    }
    __syncthreads();
    int p  = blockIdx.x * 4 + (tid >> 6);   // flattened (b,i)
    int m  = tid & 63;
    int b  = p >> 12, i = p & 4095;
    int ih = i >> 6, iw = i & 63;
    float x = bmap[b * 16384 + (ih * 2) * 128 + iw * 2];
    float t = fmaxf(x * sA[m] + sC[m], 0.f);
    g_T[(size_t)p * MID + m] = __float2bfloat16(t);
}

// ---------------- generic TN bf16 GEMM: C[m][n] = sum_k A[m][k] B[n][k] ----------------
// BM=BN=128, BK=64, 256 threads (2x4 warps, warp tile 64x32), smem XOR-swizzled.
// OUT_MODE 0: store bf16 to Cb ([b][m][n], ld=N)
// OUT_MODE 1: Cf[b][m][n] = gamma*acc + Ures[b][m][n] (f32)
template <int OUT_MODE>
__global__ __launch_bounds__(256)
void k_gemm_tn(const __nv_bfloat16* __restrict__ A, long strideA,
               const __nv_bfloat16* __restrict__ Bm, long strideB,
               int lda, int ldb, int M, int N, int K,
               __nv_bfloat16* __restrict__ Cb, long strideC,
               float* __restrict__ Cf, const float* __restrict__ Ures,
               const float* __restrict__ gamma) {
    __shared__ __align__(16) __nv_bfloat16 As[128 * 64];
    __shared__ __align__(16) __nv_bfloat16 Bs[128 * 64];

    int b  = blockIdx.z;
    int n0 = blockIdx.x * 128, m0 = blockIdx.y * 128;
    const __nv_bfloat16* Ab = A + (size_t)b * strideA;
    const __nv_bfloat16* Bb = Bm + (size_t)b * strideB;

    int tid = threadIdx.x;
    int warp = tid >> 5, lane = tid & 31;
    int wm = warp >> 2, wn = warp & 3;  // 2 x 4 warp grid

    float acc[4][4][4];
#pragma unroll
    for (int a = 0; a < 4; a++)
#pragma unroll
        for (int c = 0; c < 4; c++)
#pragma unroll
            for (int d = 0; d < 4; d++) acc[a][c][d] = 0.f;

    uint32_t sA = smem_u32(As), sB = smem_u32(Bs);

    for (int k0 = 0; k0 < K; k0 += 64) {
        // load tiles (16B chunks, XOR swizzle: chunk' = chunk ^ (row & 7))
#pragma unroll
        for (int it = 0; it < 4; it++) {
            int q = tid + it * 256;
            int r = q >> 3, c = q & 7;
            uint4 v = *reinterpret_cast<const uint4*>(Ab + (size_t)(m0 + r) * lda + k0 + c * 8);
            *reinterpret_cast<uint4*>(As + r * 64 + ((c ^ (r & 7)) << 3)) = v;
        }
#pragma unroll
        for (int it = 0; it < 4; it++) {
            int q = tid + it * 256;
            int r = q >> 3, c = q & 7;
            uint4 v = *reinterpret_cast<const uint4*>(Bb + (size_t)(n0 + r) * ldb + k0 + c * 8);
            *reinterpret_cast<uint4*>(Bs + r * 64 + ((c ^ (r & 7)) << 3)) = v;
        }
        __syncthreads();

#pragma unroll
        for (int kk = 0; kk < 4; kk++) {
            uint32_t afr[4][4];
#pragma unroll
            for (int mi = 0; mi < 4; mi++) {
                int row = wm * 64 + mi * 16 + (lane & 15);
                int ch  = kk * 2 + (lane >> 4);
                uint32_t ad = sA + ((row << 6) + ((ch ^ (row & 7)) << 3)) * 2;
                ldsm4(afr[mi][0], afr[mi][1], afr[mi][2], afr[mi][3], ad);
            }
            uint32_t bfr[4][2];
#pragma unroll
            for (int nb = 0; nb < 2; nb++) {
                int row = wn * 32 + nb * 16 + (lane & 7) + ((lane >> 4) << 3);
                int ch  = kk * 2 + ((lane >> 3) & 1);
                uint32_t ad = sB + ((row << 6) + ((ch ^ (row & 7)) << 3)) * 2;
                uint32_t r0, r1, r2, r3;
                ldsm4(r0, r1, r2, r3, ad);
                bfr[nb * 2][0] = r0; bfr[nb * 2][1] = r1;
                bfr[nb * 2 + 1][0] = r2; bfr[nb * 2 + 1][1] = r3;
            }
#pragma unroll
            for (int mi = 0; mi < 4; mi++)
#pragma unroll
                for (int ni = 0; ni < 4; ni++)
                    mma_bf16(acc[mi][ni], afr[mi][0], afr[mi][1], afr[mi][2], afr[mi][3],
                             bfr[ni][0], bfr[ni][1]);
        }
        __syncthreads();
    }

    // epilogue
    int mb = m0 + wm * 64;
    int nb = n0 + wn * 32;
    float g = 0.f;
    if (OUT_MODE == 1) g = gamma[0];
#pragma unroll
    for (int mi = 0; mi < 4; mi++) {
#pragma unroll
        for (int ni = 0; ni < 4; ni++) {
            int m = mb + mi * 16 + (lane >> 2);
            int n = nb + ni * 8 + (lane & 3) * 2;
            float* a = acc[mi][ni];
            if (OUT_MODE == 0) {
                __nv_bfloat16* base = Cb + (size_t)b * strideC;
                *reinterpret_cast<__nv_bfloat162*>(base + (size_t)m * N + n) =
                    __float22bfloat162_rn(make_float2(a[0], a[1]));
                *reinterpret_cast<__nv_bfloat162*>(base + (size_t)(m + 8) * N + n) =
                    __float22bfloat162_rn(make_float2(a[2], a[3]));
            } else {
                size_t o1 = (size_t)b * M * N + (size_t)m * N + n;
                size_t o2 = o1 + 8 * (size_t)N;
                float2 u1 = *reinterpret_cast<const float2*>(Ures + o1);
                float2 u2 = *reinterpret_cast<const float2*>(Ures + o2);
                float2 r1 = make_float2(g * a[0] + u1.x, g * a[1] + u1.y);
                float2 r2 = make_float2(g * a[2] + u2.x, g * a[3] + u2.y);
                *reinterpret_cast<float2*>(Cf + o1) = r1;
                *reinterpret_cast<float2*>(Cf + o2) = r2;
            }
        }
    }
}

// ---------------- softmax over j (per column i of S[b][j][i]) ----------------
__global__ void k_stats_partial() {
    int b = blockIdx.z, js = blockIdx.y, ib = blockIdx.x;
    int i = ib * 256 + threadIdx.x;
    const __nv_bfloat16* Sb = g_S + (size_t)b * HWN * HWN + i;
    float m = -1e30f, z = 0.f;
    int j0 = js * 256;
    for (int j = 0; j < 256; j++) {
        float s  = __bfloat162float(Sb[(size_t)(j0 + j) * HWN]);
        float mo = m;
        m = fmaxf(m, s);
        z = z * __expf(mo - m) + __expf(s - m);
    }
    g_pm[(b * 16 + js) * HWN + i] = m;
    g_pz[(b * 16 + js) * HWN + i] = z;
}

__global__ void k_stats_combine() {
    int idx = blockIdx.x * blockDim.x + threadIdx.x;  // b*4096 + i
    int b = idx >> 12, i = idx & 4095;
    float m = -1e30f;
#pragma unroll
    for (int p = 0; p < 16; p++) m = fmaxf(m, g_pm[(b * 16 + p) * HWN + i]);
    float z = 0.f;
#pragma unroll
    for (int p = 0; p < 16; p++)
        z += g_pz[(b * 16 + p) * HWN + i] * __expf(g_pm[(b * 16 + p) * HWN + i] - m);
    g_M[idx]  = m;
    g_Zi[idx] = 1.f / z;
}

// S[b][j][i] <- exp(S - m_i) * zinv_i  (in place, 8 bf16 per thread)
__global__ void k_normalize() {
    size_t t   = (size_t)blockIdx.x * blockDim.x + threadIdx.x;
    size_t off = t * 8;
    int b  = (int)(off >> 24);          // 4096*4096 = 2^24
    int i0 = (int)(off & 4095);
    uint4 v = *reinterpret_cast<const uint4*>(g_S + off);
    const float* Mb = g_M + b * HWN + i0;
    const float* Zb = g_Zi + b * HWN + i0;
    __nv_bfloat162* h = reinterpret_cast<__nv_bfloat162*>(&v);
    uint4 w;
    __nv_bfloat162* ho = reinterpret_cast<__nv_bfloat162*>(&w);
#pragma unroll
    for (int q = 0; q < 4; q++) {
        float2 f = __bfloat1622float2(h[q]);
        float p0 = __expf(f.x - Mb[q * 2 + 0]) * Zb[q * 2 + 0];
        float p1 = __expf(f.y - Mb[q * 2 + 1]) * Zb[q * 2 + 1];
        ho[q] = __float22bfloat162_rn(make_float2(p0, p1));
    }
    *reinterpret_cast<uint4*>(g_S + off) = w;
}

// ---------------- launch ----------------
extern "C" void kernel_launch(void* const* d_in, const int* in_sizes, int n_in,
                              void* d_out, int out_size) {
    const float* bmap = (const float*)d_in[0];
    const float* U    = (const float*)d_in[1];
    const float* kw1  = (const float*)d_in[2];
    const float* bsc  = (const float*)d_in[3];
    const float* bbi  = (const float*)d_in[4];
    const float* bmu  = (const float*)d_in[5];
    const float* bva  = (const float*)d_in[6];
    const float* w2   = (const float*)d_in[7];
    const float* wq   = (const float*)d_in[8];
    const float* wv   = (const float*)d_in[9];
    const float* gam  = (const float*)d_in[10];
    float* out = (float*)d_out;

    void *pUt, *pQt, *pKt, *pV, *pT, *pS, *pWq, *pWv, *pW2;
    cudaGetSymbolAddress(&pUt, g_Ut);
    cudaGetSymbolAddress(&pQt, g_Qt);
    cudaGetSymbolAddress(&pKt, g_Kt);
    cudaGetSymbolAddress(&pV,  g_V);
    cudaGetSymbolAddress(&pT,  g_T);
    cudaGetSymbolAddress(&pS,  g_S);
    cudaGetSymbolAddress(&pWq, g_Wq);
    cudaGetSymbolAddress(&pWv, g_Wv);
    cudaGetSymbolAddress(&pW2, g_W2);
    __nv_bfloat16* Ut = (__nv_bfloat16*)pUt;
    __nv_bfloat16* Qt = (__nv_bfloat16*)pQt;
    __nv_bfloat16* Kt = (__nv_bfloat16*)pKt;
    __nv_bfloat16* V  = (__nv_bfloat16*)pV;
    __nv_bfloat16* T  = (__nv_bfloat16*)pT;
    __nv_bfloat16* S  = (__nv_bfloat16*)pS;
    __nv_bfloat16* Wq = (__nv_bfloat16*)pWq;
    __nv_bfloat16* Wv = (__nv_bfloat16*)pWv;
    __nv_bfloat16* W2 = (__nv_bfloat16*)pW2;

    k_prep_weights<<<256, 256>>>(wq, wv, w2);
    k_transpose_U<<<dim3(128, 8, BATCH), dim3(32, 8)>>>(U);
    k_compute_T<<<4096, 256>>>(bmap, kw1, bsc, bbi, bmu, bva);

    // Qt[b][j][o] = sum_c Ut[j][c] * Wq[o][c]          M=4096 N=256 K=256
    k_gemm_tn<0><<<dim3(2, 32, BATCH), 256>>>(Ut, (long)HWN * CCH, Wq, 0,
                                              CCH, CCH, HWN, CCH, CCH,
                                              Qt, (long)HWN * CCH, nullptr, nullptr, nullptr);
    // Kt[b][i][o] = sum_m T[i][m] * W2[o][m]           M=4096 N=256 K=64
    k_gemm_tn<0><<<dim3(2, 32, BATCH), 256>>>(T, (long)HWN * MID, W2, 0,
                                              MID, MID, HWN, CCH, MID,
                                              Kt, (long)HWN * CCH, nullptr, nullptr, nullptr);
    // V[b][o][j] = sum_c Wv[o][c] * Ut[j][c]           M=256 N=4096 K=256
    k_gemm_tn<0><<<dim3(32, 2, BATCH), 256>>>(Wv, 0, Ut, (long)HWN * CCH,
                                              CCH, CCH, CCH, HWN, CCH,
                                              V, (long)CCH * HWN, nullptr, nullptr, nullptr);
    // S[b][j][i] = sum_o Qt[j][o] * Kt[i][o]           M=4096 N=4096 K=256
    k_gemm_tn<0><<<dim3(32, 32, BATCH), 256>>>(Qt, (long)HWN * CCH, Kt, (long)HWN * CCH,
                                               CCH, CCH, HWN, HWN, CCH,
                                               S, (long)HWN * HWN, nullptr, nullptr, nullptr);

    k_stats_partial<<<dim3(16, 16, BATCH), 256>>>();
    k_stats_combine<<<64, 256>>>();
    k_normalize<<<32768, 256>>>();

    // out[b][c][j] = gamma * sum_i V[c][i] * P[j][i] + U[b][c][j]   M=256 N=4096 K=4096
    k_gemm_tn<1><<<dim3(32, 2, BATCH), 256>>>(V, (long)CCH * HWN, S, (long)HWN * HWN,
                                              HWN, HWN, CCH, HWN, HWN,
                                              nullptr, 0, out, U, gam);
}